// round 15
// baseline (speedup 1.0000x reference)
#include <cuda_runtime.h>
#include <math.h>
#include <stdint.h>

#define BB     32
#define NN     8732
#define NCLS   20
#define DCOL   33
#define NMSMAX 100
#define TOPK   200
#define CONF_T 0.01f
#define IOU_T  0.45f
#define TILE   128
#define NTILES 69            // ceil(8732/128)
#define NBC    (BB * NCLS)   // 640
#define CAP    384
#define STAGE  64
#define TK_T   256

// ---------------- scratch ----------------
__device__ float4             g_boxes   [(size_t)BB * NN];
__device__ int                g_candcnt [NBC];            // zero-init; topk resets
__device__ unsigned long long g_cand    [NBC * CAP];
__device__ float              g_selscore[NBC * NMSMAX];
__device__ float4             g_selbox  [NBC * NMSMAX];

// monotonic float <-> u32 order-preserving map
__device__ __forceinline__ unsigned fmap(float f) {
    unsigned u = __float_as_uint(f);
    return (u & 0x80000000u) ? ~u : (u | 0x80000000u);
}
__device__ __forceinline__ float funmap(unsigned u) {
    return __uint_as_float((u & 0x80000000u) ? (u & 0x7FFFFFFFu) : ~u);
}
#define FM_NEGINF 0x007FFFFFu   // fmap(-inf)

__device__ __forceinline__ float4 decode_box_row(const float* __restrict__ r)
{
    float cx_p = r[21], cy_p = r[22], w_p = r[23], h_p = r[24];
    float xa1  = r[25], ya1  = r[26], xa2 = r[27], ya2 = r[28];
    float vcx  = r[29], vcy  = r[30], vw  = r[31], vh  = r[32];
    float w_a = xa2 - xa1, h_a = ya2 - ya1;
    float cx_a = (xa2 + xa1) * 0.5f, cy_a = (ya2 + ya1) * 0.5f;
    float cx = cx_p * vcx * w_a + cx_a;
    float cy = cy_p * vcy * h_a + cy_a;
    float w  = expf(w_p * vw) * w_a;
    float h  = expf(h_p * vh) * h_a;
    float4 o;
    o.x = (cx - 0.5f * w) * 512.0f;
    o.y = (cy - 0.5f * h) * 512.0f;
    o.z = (cx + 0.5f * w) * 512.0f;
    o.w = (cy + 0.5f * h) * 512.0f;
    return o;
}

// ---------------- phase 1: decode + staged candidate filter ----------------
__global__ void __launch_bounds__(256) decode_kernel(const float* __restrict__ y)
{
    __shared__ __align__(16) float sh[TILE * DCOL];
    __shared__ unsigned long long s_skey[NCLS * STAGE];
    __shared__ int s_scnt[NCLS];
    __shared__ int s_sbase[NCLS];

    const int tid = threadIdx.x;
    int blk = blockIdx.x;
    int b   = blk / NTILES;
    int t   = blk % NTILES;
    int n0  = t * TILE;
    int count = min(TILE, NN - n0);

    {   // vectorized tile load (count*DCOL % 4 == 0, base 16B-aligned)
        const float4* src4 = (const float4*)(y + ((size_t)b * NN + n0) * DCOL);
        float4* sh4 = (float4*)sh;
        int n4 = (count * DCOL) >> 2;
        for (int i = tid; i < n4; i += 256) sh4[i] = src4[i];
    }
    if (tid < NCLS) s_scnt[tid] = 0;
    __syncthreads();

    const unsigned LO = fmap(0.975f);
    if (count == TILE) {
        for (int k = tid; k < NCLS * TILE; k += 256) {
            int c  = k >> 7;
            int nn = k & (TILE - 1);
            float s = sh[nn * DCOL + 1 + c];
            if (s > CONF_T) {
                unsigned m = fmap(s);
                if (m >= LO) {
                    unsigned long long key = ((unsigned long long)m << 32) |
                                             (unsigned)(0xFFFFFFFFu - (unsigned)(n0 + nn));
                    int p = atomicAdd(&s_scnt[c], 1);
                    if (p < STAGE) s_skey[c * STAGE + p] = key;
                    else {
                        int bc = b * NCLS + c;
                        int q = atomicAdd(&g_candcnt[bc], 1);
                        if (q < CAP) g_cand[bc * CAP + q] = key;
                    }
                }
            }
        }
    } else {
        for (int k = tid; k < NCLS * count; k += 256) {
            int c  = k / count;
            int nn = k - c * count;
            float s = sh[nn * DCOL + 1 + c];
            if (s > CONF_T) {
                unsigned m = fmap(s);
                if (m >= LO) {
                    unsigned long long key = ((unsigned long long)m << 32) |
                                             (unsigned)(0xFFFFFFFFu - (unsigned)(n0 + nn));
                    int p = atomicAdd(&s_scnt[c], 1);
                    if (p < STAGE) s_skey[c * STAGE + p] = key;
                    else {
                        int bc = b * NCLS + c;
                        int q = atomicAdd(&g_candcnt[bc], 1);
                        if (q < CAP) g_cand[bc * CAP + q] = key;
                    }
                }
            }
        }
    }
    __syncthreads();

    if (tid < NCLS) {
        int n = min(s_scnt[tid], STAGE);
        s_sbase[tid] = (n > 0) ? atomicAdd(&g_candcnt[b * NCLS + tid], n) : 0;
    }
    __syncthreads();
    for (int k = tid; k < NCLS * STAGE; k += 256) {
        int c = k >> 6;
        int j = k & (STAGE - 1);
        if (j < min(s_scnt[c], STAGE)) {
            int q = s_sbase[c] + j;
            if (q < CAP) g_cand[(b * NCLS + c) * CAP + q] = s_skey[c * STAGE + j];
        }
    }

    if (tid < count)
        g_boxes[(size_t)b * NN + n0 + tid] = decode_box_row(sh + tid * DCOL);
}

// ---------------- phase 2: warp-scoped NMS, ONE warp-block per (b,c) --------
struct WarpSmem {
    float4   allbox[512];    // boxes in sorted order
    float4   kbox[NMSMAX];   // kept positive-area boxes (persist across windows)
    float    karea[NMSMAX];
    unsigned keyA[256];      // 32-bit compressed keys, window A
    unsigned keyB[256];      // 32-bit compressed keys, window B
};

// -------- 64-bit exact path (R11-proven): sort + serial greedy --------------
template<int SLOTS>
__device__ __forceinline__ void process_window_impl(
    const unsigned long long* __restrict__ src, int cnt, const float4* __restrict__ bx,
    int bc, WarpSmem& W, int lane, int& ns, int& nkp)
{
    constexpr int LOG2N = (SLOTS == 8) ? 8 : 9;

    unsigned long long key[SLOTS];
    #pragma unroll
    for (int s = 0; s < SLOTS; ++s) {
        int p = s * 32 + lane;
        key[s] = (p < cnt) ? src[p] : 0ull;
    }
    #pragma unroll
    for (int ksl = 1; ksl <= LOG2N; ++ksl) {
        const int ks = 1 << ksl;
        #pragma unroll
        for (int j = ks >> 1; j >= 32; j >>= 1) {
            const int js = j >> 5;
            #pragma unroll
            for (int s = 0; s < SLOTS; ++s) {
                const int sp = s ^ js;
                if (sp > s) {
                    bool descSeg = (((s * 32) & ks) == 0);
                    unsigned long long a = key[s], b2 = key[sp];
                    if (descSeg ? (a < b2) : (a > b2)) { key[s] = b2; key[sp] = a; }
                }
            }
        }
        for (int j = (ks >> 1) < 32 ? (ks >> 1) : 16; j > 0; j >>= 1) {
            #pragma unroll
            for (int s = 0; s < SLOTS; ++s) {
                int p = s * 32 + lane;
                unsigned long long pv = __shfl_xor_sync(0xFFFFFFFFu, key[s], j);
                bool takeMax = (((lane & j) == 0) == ((p & ks) == 0));
                unsigned long long mx = (key[s] > pv) ? key[s] : pv;
                unsigned long long mn = (key[s] > pv) ? pv : key[s];
                key[s] = takeMax ? mx : mn;
            }
        }
    }

    float area[SLOTS];
    #pragma unroll
    for (int s = 0; s < SLOTS; ++s) {
        int p = s * 32 + lane;
        float4 Bt = make_float4(0.f, 0.f, 0.f, 0.f);
        if (key[s] != 0ull) {
            int idx = (int)(0xFFFFFFFFu - (unsigned)(key[s] & 0xFFFFFFFFull));
            Bt = __ldg(&bx[idx]);
        }
        W.allbox[p] = Bt;
        area[s] = fmaxf(Bt.z - Bt.x, 0.0f) * fmaxf(Bt.w - Bt.y, 0.0f);
    }
    __syncwarp();

    #pragma unroll 1
    for (int s = 0; s < SLOTS; ++s) {
        if (ns >= NMSMAX) break;
        unsigned validm = __ballot_sync(0xFFFFFFFFu, key[s] != 0ull);
        if (!validm) break;
        unsigned zerom  = __ballot_sync(0xFFFFFFFFu, area[s] == 0.0f) & validm;
        unsigned posm   = validm & ~zerom;
        unsigned km = zerom;
        while (posm) {
            int l = __ffs(posm) - 1;
            posm &= posm - 1u;
            float4 Bt = W.allbox[s * 32 + l];
            float  at = __shfl_sync(0xFFFFFFFFu, area[s], l);
            bool sup = false;
            for (int j2 = lane; j2 < nkp; j2 += 32) {
                float4 Kj = W.kbox[j2];
                float ix1 = fmaxf(Kj.x, Bt.x), iy1 = fmaxf(Kj.y, Bt.y);
                float ix2 = fminf(Kj.z, Bt.z), iy2 = fminf(Kj.w, Bt.w);
                float inter = fmaxf(ix2 - ix1, 0.0f) * fmaxf(iy2 - iy1, 0.0f);
                float iou = inter / (W.karea[j2] + at - inter + 1e-9f);
                sup |= (iou > IOU_T);
            }
            if (!__any_sync(0xFFFFFFFFu, sup)) {
                km |= 1u << l;
                if (nkp < NMSMAX) {
                    if (lane == 0) { W.kbox[nkp] = Bt; W.karea[nkp] = at; }
                    nkp++;
                    __syncwarp();
                }
            }
        }
        int myr = ns + __popc(km & ((1u << lane) - 1u));
        if (((km >> lane) & 1u) && myr < NMSMAX) {
            int o = bc * NMSMAX + myr;
            g_selscore[o] = funmap((unsigned)(key[s] >> 32));
            g_selbox[o]   = W.allbox[s * 32 + lane];
        }
        ns += __popc(km);
    }
}

__device__ __noinline__ void process_window8(
    const unsigned long long* src, int cnt, const float4* bx,
    int bc, WarpSmem& W, int lane, int& ns, int& nkp)
{ process_window_impl<8>(src, cnt, bx, bc, W, lane, ns, nkp); }

__device__ __noinline__ void process_window16(
    const unsigned long long* src, int cnt, const float4* bx,
    int bc, WarpSmem& W, int lane, int& ns, int& nkp)
{ process_window_impl<16>(src, cnt, bx, bc, W, lane, ns, nkp); }

// -------- 32-bit compressed-key fast path with slot-parallel greedy --------
// key32 = ((m - base) << 14) | (16383 - idx); requires m - base < 2^18
// (guaranteed by the window split) and idx <= 8731 < 2^14.
template<int SLOTS>
__device__ __forceinline__ void process32_impl(
    const unsigned* __restrict__ skey, int cnt, unsigned base,
    const float4* __restrict__ bx, int bc, WarpSmem& W, int lane, int& ns, int& nkp)
{
    constexpr int LOG2N = (SLOTS == 4) ? 7 : 8;

    unsigned key[SLOTS];
    #pragma unroll
    for (int s = 0; s < SLOTS; ++s) {
        int p = s * 32 + lane;
        key[s] = (p < cnt) ? skey[p] : 0u;
    }

    // ---- warp bitonic sort (32-bit), descending ----
    #pragma unroll
    for (int ksl = 1; ksl <= LOG2N; ++ksl) {
        const int ks = 1 << ksl;
        #pragma unroll
        for (int j = ks >> 1; j >= 32; j >>= 1) {
            const int js = j >> 5;
            #pragma unroll
            for (int s = 0; s < SLOTS; ++s) {
                const int sp = s ^ js;
                if (sp > s) {
                    bool descSeg = (((s * 32) & ks) == 0);
                    unsigned a = key[s], b2 = key[sp];
                    if (descSeg ? (a < b2) : (a > b2)) { key[s] = b2; key[sp] = a; }
                }
            }
        }
        for (int j = (ks >> 1) < 32 ? (ks >> 1) : 16; j > 0; j >>= 1) {
            #pragma unroll
            for (int s = 0; s < SLOTS; ++s) {
                int p = s * 32 + lane;
                unsigned pv = __shfl_xor_sync(0xFFFFFFFFu, key[s], j);
                bool takeMax = (((lane & j) == 0) == ((p & ks) == 0));
                unsigned mx = (key[s] > pv) ? key[s] : pv;
                unsigned mn = (key[s] > pv) ? pv : key[s];
                key[s] = takeMax ? mx : mn;
            }
        }
    }

    // ---- fetch boxes + areas in sorted order ----
    float area[SLOTS];
    #pragma unroll
    for (int s = 0; s < SLOTS; ++s) {
        int p = s * 32 + lane;
        float4 Bt = make_float4(0.f, 0.f, 0.f, 0.f);
        if (key[s] != 0u) {
            int idx = 16383 - (int)(key[s] & 0x3FFFu);
            Bt = __ldg(&bx[idx]);
        }
        W.allbox[p] = Bt;
        area[s] = fmaxf(Bt.z - Bt.x, 0.0f) * fmaxf(Bt.w - Bt.y, 0.0f);
    }
    __syncwarp();

    // ---- slot-parallel greedy ----
    // zeros (IOU==0 with everything) auto-kept and never suppress; each lane
    // tests ITS OWN positive vs the prior kept-positive list and vs earlier
    // positives of the same slot; a short register resolve finishes the order.
    #pragma unroll 1
    for (int s = 0; s < SLOTS; ++s) {
        if (ns >= NMSMAX) break;                   // exact: later ranks >= 100
        unsigned validm = __ballot_sync(0xFFFFFFFFu, key[s] != 0u);
        if (!validm) break;                        // sorted: rest empty
        unsigned zerom  = __ballot_sync(0xFFFFFFFFu, area[s] == 0.0f) & validm;
        unsigned posm   = validm & ~zerom;
        unsigned keptpos = 0;
        if (posm) {
            bool supk = false;
            unsigned pairm = 0;
            if ((posm >> lane) & 1u) {
                float4 Bown = W.allbox[s * 32 + lane];
                float  at = area[s];
                for (int j = 0; j < nkp; ++j) {        // prior kept positives
                    float4 Kj = W.kbox[j];
                    float ix1 = fmaxf(Kj.x, Bown.x), iy1 = fmaxf(Kj.y, Bown.y);
                    float ix2 = fminf(Kj.z, Bown.z), iy2 = fminf(Kj.w, Bown.w);
                    float inter = fmaxf(ix2 - ix1, 0.0f) * fmaxf(iy2 - iy1, 0.0f);
                    float iou = inter / (W.karea[j] + at - inter + 1e-9f);
                    supk |= (iou > IOU_T);
                }
                unsigned earlier = posm & ((1u << lane) - 1u);
                while (earlier) {                      // earlier positives, same slot
                    int i = __ffs(earlier) - 1;
                    earlier &= earlier - 1u;
                    float4 Bi = W.allbox[s * 32 + i];
                    float ai = fmaxf(Bi.z - Bi.x, 0.0f) * fmaxf(Bi.w - Bi.y, 0.0f);
                    float ix1 = fmaxf(Bi.x, Bown.x), iy1 = fmaxf(Bi.y, Bown.y);
                    float ix2 = fminf(Bi.z, Bown.z), iy2 = fminf(Bi.w, Bown.w);
                    float inter = fmaxf(ix2 - ix1, 0.0f) * fmaxf(iy2 - iy1, 0.0f);
                    float iou = inter / (ai + at - inter + 1e-9f);
                    if (iou > IOU_T) pairm |= 1u << i;
                }
            }
            unsigned supkm = __ballot_sync(0xFFFFFFFFu, supk);
            unsigned rem = posm;
            while (rem) {                              // register bitmask resolve
                int l = __ffs(rem) - 1;
                rem &= rem - 1u;
                unsigned pm = __shfl_sync(0xFFFFFFFFu, pairm, l);
                bool sup = ((supkm >> l) & 1u) || ((pm & keptpos) != 0u);
                if (!sup) keptpos |= 1u << l;
            }
            if ((keptpos >> lane) & 1u) {              // parallel kept insert
                int r = nkp + __popc(keptpos & ((1u << lane) - 1u));
                if (r < NMSMAX) {
                    W.kbox[r]  = W.allbox[s * 32 + lane];
                    W.karea[r] = area[s];
                }
            }
            nkp = min(nkp + __popc(keptpos), NMSMAX);
            __syncwarp();
        }
        unsigned km = zerom | keptpos;
        int myr = ns + __popc(km & ((1u << lane) - 1u));
        if (((km >> lane) & 1u) && myr < NMSMAX) {
            int o = bc * NMSMAX + myr;
            g_selscore[o] = funmap(base + (key[s] >> 14));
            g_selbox[o]   = W.allbox[s * 32 + lane];
        }
        ns += __popc(km);
    }
}

__device__ __forceinline__ void process32_4(
    const unsigned* skey, int cnt, unsigned base, const float4* bx,
    int bc, WarpSmem& W, int lane, int& ns, int& nkp)
{ process32_impl<4>(skey, cnt, base, bx, bc, W, lane, ns, nkp); }

__device__ __noinline__ void process32_8(
    const unsigned* skey, int cnt, unsigned base, const float4* bx,
    int bc, WarpSmem& W, int lane, int& ns, int& nkp)
{ process32_impl<8>(skey, cnt, base, bx, bc, W, lane, ns, nkp); }

__global__ void __launch_bounds__(32) nms_kernel(const float* __restrict__ y)
{
    __shared__ WarpSmem W;
    const int lane = threadIdx.x;
    const int bc   = blockIdx.x;
    const int b    = bc / NCLS;
    const int c    = bc - b * NCLS;
    const float4* bx = g_boxes + (size_t)b * NN;

    const unsigned LO  = fmap(0.975f);
    const unsigned HI2 = fmap(0.9875f);
    const unsigned below = (1u << lane) - 1u;
    int ns = 0, nkp = 0;

    int cnt0 = g_candcnt[bc];
    bool haveList = (cnt0 <= CAP);
    unsigned nextHi = haveList ? LO : 0xFFFFFFFFu;

    if (haveList && cnt0 > 0) {
        // partition list into A=[0.9875,1) and B=[0.975,0.9875) as 32-bit keys
        const unsigned long long* src = g_cand + bc * CAP;
        int cA = 0, cB = 0;
        for (int s = 0; s * 32 < cnt0; ++s) {
            int p = s * 32 + lane;
            unsigned long long k = (p < cnt0) ? src[p] : 0ull;
            unsigned m = (unsigned)(k >> 32);
            bool valid = (p < cnt0);
            bool inA = valid && (m >= HI2);
            bool inB = valid && (m < HI2);
            unsigned mA = __ballot_sync(0xFFFFFFFFu, inA);
            unsigned mB = __ballot_sync(0xFFFFFFFFu, inB);
            unsigned inv14 = (unsigned)k & 0x3FFFu;
            if (inA) {
                int q = cA + __popc(mA & below);
                if (q < 256) W.keyA[q] = ((m - HI2) << 14) | inv14;
            }
            if (inB) {
                int q = cB + __popc(mB & below);
                if (q < 256) W.keyB[q] = ((m - LO) << 14) | inv14;
            }
            cA += __popc(mA);
            cB += __popc(mB);
        }
        __syncwarp();

        if (cA <= 256 && cB <= 256) {
            if (cA > 0) {
                if (cA <= 128) process32_4(W.keyA, cA, HI2, bx, bc, W, lane, ns, nkp);
                else           process32_8(W.keyA, cA, HI2, bx, bc, W, lane, ns, nkp);
            }
            if (ns < NMSMAX && cB > 0) {
                if (cB <= 128) process32_4(W.keyB, cB, LO, bx, bc, W, lane, ns, nkp);
                else           process32_8(W.keyB, cB, LO, bx, bc, W, lane, ns, nkp);
            }
        } else {
            // extreme skew: 64-bit whole-list exact path
            if (cnt0 <= 256) process_window8 (src, cnt0, bx, bc, W, lane, ns, nkp);
            else             process_window16(src, cnt0, bx, bc, W, lane, ns, nkp);
        }
    }

    // exact continuation: descend score windows over raw y (warp-scoped, rare)
    while (ns < NMSMAX && nextHi > 0) {
        unsigned lo2 = 0, hi2 = nextHi;
        int cnt;
        for (;;) {
            cnt = 0;
            for (int i = lane; i < NN; i += 32) {
                float v = y[((size_t)b * NN + i) * DCOL + 1 + c];
                bool take = false; unsigned m = 0;
                if (v > CONF_T) { m = fmap(v); take = (m >= lo2 && m < hi2); }
                unsigned msk = __ballot_sync(0xFFFFFFFFu, take);
                if (take) {
                    int off = cnt + __popc(msk & below);
                    if (off < CAP)
                        g_cand[bc * CAP + off] = ((unsigned long long)m << 32) |
                                                 (unsigned)(0xFFFFFFFFu - (unsigned)i);
                }
                cnt += __popc(msk);
            }
            if (cnt <= CAP || hi2 - lo2 <= 1) break;
            lo2 = lo2 + ((hi2 - lo2) >> 1);
        }
        if (cnt > CAP) cnt = CAP;
        __threadfence_block();
        __syncwarp();
        if (cnt > 0) {
            if (cnt <= 256) process_window8 (g_cand + bc * CAP, cnt, bx, bc, W, lane, ns, nkp);
            else            process_window16(g_cand + bc * CAP, cnt, bx, bc, W, lane, ns, nkp);
        }
        nextHi = lo2;
    }

    for (int j = ns + lane; j < NMSMAX; j += 32)
        g_selscore[bc * NMSMAX + j] = -INFINITY;
}

// ---------------- phase 3: rank-scatter top-200 (R11 measured-best) ---------
__global__ void __launch_bounds__(TK_T) topk_kernel(float* __restrict__ out)
{
    const int bc  = blockIdx.x;
    const int b   = bc / NCLS;
    const int c0  = bc - b * NCLS;
    const int tid = threadIdx.x;
    const int NK  = NCLS * NMSMAX;

    __shared__ unsigned long long keys[NCLS * NMSMAX];
    __shared__ int s_rank[NMSMAX];

    for (int k = tid; k < NK; k += TK_T) {
        float s = g_selscore[b * NK + k];
        keys[k] = ((unsigned long long)fmap(s) << 32) |
                  (unsigned)(0xFFFFFFFFu - (unsigned)k);
    }
    if (tid < NMSMAX) s_rank[tid] = tid;
    __syncthreads();

    for (int u = tid; u < (NCLS - 1) * NMSMAX; u += TK_T) {
        int j = u / NMSMAX;
        int i = u - j * NMSMAX;
        int cc = j + (j >= c0);
        unsigned long long my = keys[c0 * NMSMAX + i];
        const unsigned long long* L = keys + cc * NMSMAX;
        int lo = 0, hi = NMSMAX;
        while (lo < hi) {
            int mid = (lo + hi) >> 1;
            if (L[mid] > my) lo = mid + 1; else hi = mid;
        }
        atomicAdd(&s_rank[i], lo);
    }
    __syncthreads();

    if (tid < NMSMAX) {
        int r = s_rank[tid];
        if (r < TOPK) {
            unsigned long long key = keys[c0 * NMSMAX + tid];
            unsigned hi32 = (unsigned)(key >> 32);
            float* o = out + ((size_t)b * TOPK + r) * 6;
            if (hi32 != FM_NEGINF) {
                float4 box = g_selbox[bc * NMSMAX + tid];
                o[0] = (float)c0 + 1.0f;
                o[1] = funmap(hi32);
                o[2] = box.x; o[3] = box.y; o[4] = box.z; o[5] = box.w;
            } else {
                o[0] = 1.0f; o[1] = 0.0f;
                o[2] = 0.0f; o[3] = 0.0f; o[4] = 0.0f; o[5] = 0.0f;
            }
        }
    }
    if (tid == 0) g_candcnt[bc] = 0;   // reset for next replay (stream-ordered)
}

// -----------------------------------------------------------------------------
extern "C" void kernel_launch(void* const* d_in, const int* in_sizes, int n_in,
                              void* d_out, int out_size)
{
    const float* y = (const float*)d_in[0];
    float* out = (float*)d_out;
    decode_kernel<<<BB * NTILES, 256>>>(y);
    nms_kernel<<<NBC, 32>>>(y);
    topk_kernel<<<NBC, TK_T>>>(out);
}

// round 16
// speedup vs baseline: 1.1480x; 1.1480x over previous
#include <cuda_runtime.h>
#include <math.h>
#include <stdint.h>

#define BB     32
#define NN     8732
#define NCLS   20
#define DCOL   33
#define NMSMAX 100
#define TOPK   200
#define CONF_T 0.01f
#define IOU_T  0.45f
#define TILE   128
#define NTILES 69            // ceil(8732/128)
#define NBC    (BB * NCLS)   // 640
#define CAP    384
#define STAGE  64
#define TK_T   256

// ---------------- scratch ----------------
__device__ float4             g_boxes   [(size_t)BB * NN];
__device__ int                g_candcnt [NBC];            // zero-init; topk resets
__device__ unsigned long long g_cand    [NBC * CAP];
__device__ float              g_selscore[NBC * NMSMAX];
__device__ float4             g_selbox  [NBC * NMSMAX];

// monotonic float <-> u32 order-preserving map
__device__ __forceinline__ unsigned fmap(float f) {
    unsigned u = __float_as_uint(f);
    return (u & 0x80000000u) ? ~u : (u | 0x80000000u);
}
__device__ __forceinline__ float funmap(unsigned u) {
    return __uint_as_float((u & 0x80000000u) ? (u & 0x7FFFFFFFu) : ~u);
}
#define FM_NEGINF 0x007FFFFFu   // fmap(-inf)

__device__ __forceinline__ float4 decode_box_row(const float* __restrict__ r)
{
    float cx_p = r[21], cy_p = r[22], w_p = r[23], h_p = r[24];
    float xa1  = r[25], ya1  = r[26], xa2 = r[27], ya2 = r[28];
    float vcx  = r[29], vcy  = r[30], vw  = r[31], vh  = r[32];
    float w_a = xa2 - xa1, h_a = ya2 - ya1;
    float cx_a = (xa2 + xa1) * 0.5f, cy_a = (ya2 + ya1) * 0.5f;
    float cx = cx_p * vcx * w_a + cx_a;
    float cy = cy_p * vcy * h_a + cy_a;
    float w  = expf(w_p * vw) * w_a;
    float h  = expf(h_p * vh) * h_a;
    float4 o;
    o.x = (cx - 0.5f * w) * 512.0f;
    o.y = (cy - 0.5f * h) * 512.0f;
    o.z = (cx + 0.5f * w) * 512.0f;
    o.w = (cy + 0.5f * h) * 512.0f;
    return o;
}

// ---------------- phase 1: decode + staged candidate filter ----------------
// Candidate condition: fmap monotonic => (s > CONF_T && fmap(s) >= fmap(0.975))
// is exactly (s >= 0.975f) — one FSETP, fmap computed only for ~2.5% taken.
__global__ void __launch_bounds__(256) decode_kernel(const float* __restrict__ y)
{
    __shared__ __align__(16) float sh[TILE * DCOL];
    __shared__ unsigned long long s_skey[NCLS * STAGE];
    __shared__ int s_scnt[NCLS];
    __shared__ int s_sbase[NCLS];

    const int tid = threadIdx.x;
    int blk = blockIdx.x;
    int b   = blk / NTILES;
    int t   = blk % NTILES;
    int n0  = t * TILE;
    int count = min(TILE, NN - n0);

    {   // vectorized tile load (count*DCOL % 4 == 0, base 16B-aligned)
        const float4* src4 = (const float4*)(y + ((size_t)b * NN + n0) * DCOL);
        float4* sh4 = (float4*)sh;
        int n4 = (count * DCOL) >> 2;
        for (int i = tid; i < n4; i += 256) sh4[i] = src4[i];
    }
    if (tid < NCLS) s_scnt[tid] = 0;
    __syncthreads();

    if (count == TILE) {
        for (int k = tid; k < NCLS * TILE; k += 256) {
            int c  = k >> 7;
            int nn = k & (TILE - 1);
            float s = sh[nn * DCOL + 1 + c];
            if (s >= 0.975f) {
                unsigned m = fmap(s);
                unsigned long long key = ((unsigned long long)m << 32) |
                                         (unsigned)(0xFFFFFFFFu - (unsigned)(n0 + nn));
                int p = atomicAdd(&s_scnt[c], 1);
                if (p < STAGE) s_skey[c * STAGE + p] = key;
                else {
                    int bc = b * NCLS + c;
                    int q = atomicAdd(&g_candcnt[bc], 1);
                    if (q < CAP) g_cand[bc * CAP + q] = key;
                }
            }
        }
    } else {
        for (int k = tid; k < NCLS * count; k += 256) {
            int c  = k / count;
            int nn = k - c * count;
            float s = sh[nn * DCOL + 1 + c];
            if (s >= 0.975f) {
                unsigned m = fmap(s);
                unsigned long long key = ((unsigned long long)m << 32) |
                                         (unsigned)(0xFFFFFFFFu - (unsigned)(n0 + nn));
                int p = atomicAdd(&s_scnt[c], 1);
                if (p < STAGE) s_skey[c * STAGE + p] = key;
                else {
                    int bc = b * NCLS + c;
                    int q = atomicAdd(&g_candcnt[bc], 1);
                    if (q < CAP) g_cand[bc * CAP + q] = key;
                }
            }
        }
    }
    __syncthreads();

    if (tid < NCLS) {
        int n = min(s_scnt[tid], STAGE);
        s_sbase[tid] = (n > 0) ? atomicAdd(&g_candcnt[b * NCLS + tid], n) : 0;
    }
    __syncthreads();
    for (int k = tid; k < NCLS * STAGE; k += 256) {
        int c = k >> 6;
        int j = k & (STAGE - 1);
        if (j < min(s_scnt[c], STAGE)) {
            int q = s_sbase[c] + j;
            if (q < CAP) g_cand[(b * NCLS + c) * CAP + q] = s_skey[c * STAGE + j];
        }
    }

    if (tid < count)
        g_boxes[(size_t)b * NN + n0 + tid] = decode_box_row(sh + tid * DCOL);
}

// ---------------- phase 2: warp-scoped NMS, ONE warp-block per (b,c) --------
struct WarpSmem {
    float4   allbox[512];    // boxes in sorted order
    float4   kbox[NMSMAX];   // kept positive-area boxes (persist across windows)
    float    karea[NMSMAX];
    unsigned keyA[256];      // 32-bit compressed keys, window A
    unsigned keyB[256];      // 32-bit compressed keys, window B
};

// -------- 64-bit exact path (R11-proven): sort + serial greedy --------------
template<int SLOTS>
__device__ __forceinline__ void process_window_impl(
    const unsigned long long* __restrict__ src, int cnt, const float4* __restrict__ bx,
    int bc, WarpSmem& W, int lane, int& ns, int& nkp)
{
    constexpr int LOG2N = (SLOTS == 8) ? 8 : 9;

    unsigned long long key[SLOTS];
    #pragma unroll
    for (int s = 0; s < SLOTS; ++s) {
        int p = s * 32 + lane;
        key[s] = (p < cnt) ? src[p] : 0ull;
    }
    #pragma unroll
    for (int ksl = 1; ksl <= LOG2N; ++ksl) {
        const int ks = 1 << ksl;
        #pragma unroll
        for (int j = ks >> 1; j >= 32; j >>= 1) {
            const int js = j >> 5;
            #pragma unroll
            for (int s = 0; s < SLOTS; ++s) {
                const int sp = s ^ js;
                if (sp > s) {
                    bool descSeg = (((s * 32) & ks) == 0);
                    unsigned long long a = key[s], b2 = key[sp];
                    if (descSeg ? (a < b2) : (a > b2)) { key[s] = b2; key[sp] = a; }
                }
            }
        }
        for (int j = (ks >> 1) < 32 ? (ks >> 1) : 16; j > 0; j >>= 1) {
            #pragma unroll
            for (int s = 0; s < SLOTS; ++s) {
                int p = s * 32 + lane;
                unsigned long long pv = __shfl_xor_sync(0xFFFFFFFFu, key[s], j);
                bool takeMax = (((lane & j) == 0) == ((p & ks) == 0));
                unsigned long long mx = (key[s] > pv) ? key[s] : pv;
                unsigned long long mn = (key[s] > pv) ? pv : key[s];
                key[s] = takeMax ? mx : mn;
            }
        }
    }

    float area[SLOTS];
    #pragma unroll
    for (int s = 0; s < SLOTS; ++s) {
        int p = s * 32 + lane;
        float4 Bt = make_float4(0.f, 0.f, 0.f, 0.f);
        if (key[s] != 0ull) {
            int idx = (int)(0xFFFFFFFFu - (unsigned)(key[s] & 0xFFFFFFFFull));
            Bt = __ldg(&bx[idx]);
        }
        W.allbox[p] = Bt;
        area[s] = fmaxf(Bt.z - Bt.x, 0.0f) * fmaxf(Bt.w - Bt.y, 0.0f);
    }
    __syncwarp();

    #pragma unroll 1
    for (int s = 0; s < SLOTS; ++s) {
        if (ns >= NMSMAX) break;
        unsigned validm = __ballot_sync(0xFFFFFFFFu, key[s] != 0ull);
        if (!validm) break;
        unsigned zerom  = __ballot_sync(0xFFFFFFFFu, area[s] == 0.0f) & validm;
        unsigned posm   = validm & ~zerom;
        unsigned km = zerom;
        while (posm) {
            int l = __ffs(posm) - 1;
            posm &= posm - 1u;
            float4 Bt = W.allbox[s * 32 + l];
            float  at = __shfl_sync(0xFFFFFFFFu, area[s], l);
            bool sup = false;
            for (int j2 = lane; j2 < nkp; j2 += 32) {
                float4 Kj = W.kbox[j2];
                float ix1 = fmaxf(Kj.x, Bt.x), iy1 = fmaxf(Kj.y, Bt.y);
                float ix2 = fminf(Kj.z, Bt.z), iy2 = fminf(Kj.w, Bt.w);
                float inter = fmaxf(ix2 - ix1, 0.0f) * fmaxf(iy2 - iy1, 0.0f);
                float iou = inter / (W.karea[j2] + at - inter + 1e-9f);
                sup |= (iou > IOU_T);
            }
            if (!__any_sync(0xFFFFFFFFu, sup)) {
                km |= 1u << l;
                if (nkp < NMSMAX) {
                    if (lane == 0) { W.kbox[nkp] = Bt; W.karea[nkp] = at; }
                    nkp++;
                    __syncwarp();
                }
            }
        }
        int myr = ns + __popc(km & ((1u << lane) - 1u));
        if (((km >> lane) & 1u) && myr < NMSMAX) {
            int o = bc * NMSMAX + myr;
            g_selscore[o] = funmap((unsigned)(key[s] >> 32));
            g_selbox[o]   = W.allbox[s * 32 + lane];
        }
        ns += __popc(km);
    }
}

__device__ __noinline__ void process_window8(
    const unsigned long long* src, int cnt, const float4* bx,
    int bc, WarpSmem& W, int lane, int& ns, int& nkp)
{ process_window_impl<8>(src, cnt, bx, bc, W, lane, ns, nkp); }

__device__ __noinline__ void process_window16(
    const unsigned long long* src, int cnt, const float4* bx,
    int bc, WarpSmem& W, int lane, int& ns, int& nkp)
{ process_window_impl<16>(src, cnt, bx, bc, W, lane, ns, nkp); }

// -------- 32-bit compressed-key fast path (R14 measured-best) ---------------
// key32 = ((m - base) << 14) | (16383 - idx); requires m - base < 2^18
// (guaranteed by the window split) and idx <= 8731 < 2^14.
// Pad key 0 cannot collide: real keys have low14 >= 16383-8731 = 7652 > 0.
template<int SLOTS>
__device__ __forceinline__ void process32_impl(
    const unsigned* __restrict__ skey, int cnt, unsigned base,
    const float4* __restrict__ bx, int bc, WarpSmem& W, int lane, int& ns, int& nkp)
{
    constexpr int LOG2N = (SLOTS == 4) ? 7 : 8;

    unsigned key[SLOTS];
    #pragma unroll
    for (int s = 0; s < SLOTS; ++s) {
        int p = s * 32 + lane;
        key[s] = (p < cnt) ? skey[p] : 0u;
    }

    // ---- warp bitonic sort (32-bit), descending ----
    #pragma unroll
    for (int ksl = 1; ksl <= LOG2N; ++ksl) {
        const int ks = 1 << ksl;
        #pragma unroll
        for (int j = ks >> 1; j >= 32; j >>= 1) {
            const int js = j >> 5;
            #pragma unroll
            for (int s = 0; s < SLOTS; ++s) {
                const int sp = s ^ js;
                if (sp > s) {
                    bool descSeg = (((s * 32) & ks) == 0);
                    unsigned a = key[s], b2 = key[sp];
                    if (descSeg ? (a < b2) : (a > b2)) { key[s] = b2; key[sp] = a; }
                }
            }
        }
        for (int j = (ks >> 1) < 32 ? (ks >> 1) : 16; j > 0; j >>= 1) {
            #pragma unroll
            for (int s = 0; s < SLOTS; ++s) {
                int p = s * 32 + lane;
                unsigned pv = __shfl_xor_sync(0xFFFFFFFFu, key[s], j);
                bool takeMax = (((lane & j) == 0) == ((p & ks) == 0));
                unsigned mx = (key[s] > pv) ? key[s] : pv;
                unsigned mn = (key[s] > pv) ? pv : key[s];
                key[s] = takeMax ? mx : mn;
            }
        }
    }

    // ---- fetch boxes + areas in sorted order ----
    float area[SLOTS];
    #pragma unroll
    for (int s = 0; s < SLOTS; ++s) {
        int p = s * 32 + lane;
        float4 Bt = make_float4(0.f, 0.f, 0.f, 0.f);
        if (key[s] != 0u) {
            int idx = 16383 - (int)(key[s] & 0x3FFFu);
            Bt = __ldg(&bx[idx]);
        }
        W.allbox[p] = Bt;
        area[s] = fmaxf(Bt.z - Bt.x, 0.0f) * fmaxf(Bt.w - Bt.y, 0.0f);
    }
    __syncwarp();

    // ---- greedy (serial, R14 measured-best) ----
    #pragma unroll 1
    for (int s = 0; s < SLOTS; ++s) {
        if (ns >= NMSMAX) break;
        unsigned validm = __ballot_sync(0xFFFFFFFFu, key[s] != 0u);
        if (!validm) break;
        unsigned zerom  = __ballot_sync(0xFFFFFFFFu, area[s] == 0.0f) & validm;
        unsigned posm   = validm & ~zerom;
        unsigned km = zerom;
        while (posm) {
            int l = __ffs(posm) - 1;
            posm &= posm - 1u;
            float4 Bt = W.allbox[s * 32 + l];
            float  at = __shfl_sync(0xFFFFFFFFu, area[s], l);
            bool sup = false;
            for (int j2 = lane; j2 < nkp; j2 += 32) {
                float4 Kj = W.kbox[j2];
                float ix1 = fmaxf(Kj.x, Bt.x), iy1 = fmaxf(Kj.y, Bt.y);
                float ix2 = fminf(Kj.z, Bt.z), iy2 = fminf(Kj.w, Bt.w);
                float inter = fmaxf(ix2 - ix1, 0.0f) * fmaxf(iy2 - iy1, 0.0f);
                float iou = inter / (W.karea[j2] + at - inter + 1e-9f);
                sup |= (iou > IOU_T);
            }
            if (!__any_sync(0xFFFFFFFFu, sup)) {
                km |= 1u << l;
                if (nkp < NMSMAX) {
                    if (lane == 0) { W.kbox[nkp] = Bt; W.karea[nkp] = at; }
                    nkp++;
                    __syncwarp();
                }
            }
        }
        int myr = ns + __popc(km & ((1u << lane) - 1u));
        if (((km >> lane) & 1u) && myr < NMSMAX) {
            int o = bc * NMSMAX + myr;
            g_selscore[o] = funmap(base + (key[s] >> 14));
            g_selbox[o]   = W.allbox[s * 32 + lane];
        }
        ns += __popc(km);
    }
}

__device__ __forceinline__ void process32_4(
    const unsigned* skey, int cnt, unsigned base, const float4* bx,
    int bc, WarpSmem& W, int lane, int& ns, int& nkp)
{ process32_impl<4>(skey, cnt, base, bx, bc, W, lane, ns, nkp); }

__device__ __noinline__ void process32_8(
    const unsigned* skey, int cnt, unsigned base, const float4* bx,
    int bc, WarpSmem& W, int lane, int& ns, int& nkp)
{ process32_impl<8>(skey, cnt, base, bx, bc, W, lane, ns, nkp); }

__global__ void __launch_bounds__(32) nms_kernel(const float* __restrict__ y)
{
    __shared__ WarpSmem W;
    const int lane = threadIdx.x;
    const int bc   = blockIdx.x;
    const int b    = bc / NCLS;
    const int c    = bc - b * NCLS;
    const float4* bx = g_boxes + (size_t)b * NN;

    const unsigned LO  = fmap(0.975f);
    const unsigned HI2 = fmap(0.9875f);
    const unsigned below = (1u << lane) - 1u;
    int ns = 0, nkp = 0;

    int cnt0 = g_candcnt[bc];
    bool haveList = (cnt0 <= CAP);
    unsigned nextHi = haveList ? LO : 0xFFFFFFFFu;

    if (haveList && cnt0 > 0) {
        // partition list into A=[0.9875,1) and B=[0.975,0.9875) as 32-bit keys
        const unsigned long long* src = g_cand + bc * CAP;
        int cA = 0, cB = 0;
        for (int s = 0; s * 32 < cnt0; ++s) {
            int p = s * 32 + lane;
            unsigned long long k = (p < cnt0) ? src[p] : 0ull;
            unsigned m = (unsigned)(k >> 32);
            bool valid = (p < cnt0);
            bool inA = valid && (m >= HI2);
            bool inB = valid && (m < HI2);
            unsigned mA = __ballot_sync(0xFFFFFFFFu, inA);
            unsigned mB = __ballot_sync(0xFFFFFFFFu, inB);
            unsigned inv14 = (unsigned)k & 0x3FFFu;
            if (inA) {
                int q = cA + __popc(mA & below);
                if (q < 256) W.keyA[q] = ((m - HI2) << 14) | inv14;
            }
            if (inB) {
                int q = cB + __popc(mB & below);
                if (q < 256) W.keyB[q] = ((m - LO) << 14) | inv14;
            }
            cA += __popc(mA);
            cB += __popc(mB);
        }
        __syncwarp();

        if (cA <= 256 && cB <= 256) {
            if (cA > 0) {
                if (cA <= 128) process32_4(W.keyA, cA, HI2, bx, bc, W, lane, ns, nkp);
                else           process32_8(W.keyA, cA, HI2, bx, bc, W, lane, ns, nkp);
            }
            if (ns < NMSMAX && cB > 0) {
                if (cB <= 128) process32_4(W.keyB, cB, LO, bx, bc, W, lane, ns, nkp);
                else           process32_8(W.keyB, cB, LO, bx, bc, W, lane, ns, nkp);
            }
        } else {
            // extreme skew: 64-bit whole-list exact path
            if (cnt0 <= 256) process_window8 (src, cnt0, bx, bc, W, lane, ns, nkp);
            else             process_window16(src, cnt0, bx, bc, W, lane, ns, nkp);
        }
    }

    // exact continuation: descend score windows over raw y (warp-scoped, rare)
    while (ns < NMSMAX && nextHi > 0) {
        unsigned lo2 = 0, hi2 = nextHi;
        int cnt;
        for (;;) {
            cnt = 0;
            for (int i = lane; i < NN; i += 32) {
                float v = y[((size_t)b * NN + i) * DCOL + 1 + c];
                bool take = false; unsigned m = 0;
                if (v > CONF_T) { m = fmap(v); take = (m >= lo2 && m < hi2); }
                unsigned msk = __ballot_sync(0xFFFFFFFFu, take);
                if (take) {
                    int off = cnt + __popc(msk & below);
                    if (off < CAP)
                        g_cand[bc * CAP + off] = ((unsigned long long)m << 32) |
                                                 (unsigned)(0xFFFFFFFFu - (unsigned)i);
                }
                cnt += __popc(msk);
            }
            if (cnt <= CAP || hi2 - lo2 <= 1) break;
            lo2 = lo2 + ((hi2 - lo2) >> 1);
        }
        if (cnt > CAP) cnt = CAP;
        __threadfence_block();
        __syncwarp();
        if (cnt > 0) {
            if (cnt <= 256) process_window8 (g_cand + bc * CAP, cnt, bx, bc, W, lane, ns, nkp);
            else            process_window16(g_cand + bc * CAP, cnt, bx, bc, W, lane, ns, nkp);
        }
        nextHi = lo2;
    }

    for (int j = ns + lane; j < NMSMAX; j += 32)
        g_selscore[bc * NMSMAX + j] = -INFINITY;
}

// ---------------- phase 3: rank-scatter top-200 (R11 measured-best) ---------
__global__ void __launch_bounds__(TK_T) topk_kernel(float* __restrict__ out)
{
    const int bc  = blockIdx.x;
    const int b   = bc / NCLS;
    const int c0  = bc - b * NCLS;
    const int tid = threadIdx.x;
    const int NK  = NCLS * NMSMAX;

    __shared__ unsigned long long keys[NCLS * NMSMAX];
    __shared__ int s_rank[NMSMAX];

    for (int k = tid; k < NK; k += TK_T) {
        float s = g_selscore[b * NK + k];
        keys[k] = ((unsigned long long)fmap(s) << 32) |
                  (unsigned)(0xFFFFFFFFu - (unsigned)k);
    }
    if (tid < NMSMAX) s_rank[tid] = tid;
    __syncthreads();

    for (int u = tid; u < (NCLS - 1) * NMSMAX; u += TK_T) {
        int j = u / NMSMAX;            // other-class slot 0..18
        int i = u - j * NMSMAX;        // own-list position 0..99
        int cc = j + (j >= c0);
        unsigned long long my = keys[c0 * NMSMAX + i];
        const unsigned long long* L = keys + cc * NMSMAX;
        int lo = 0, hi = NMSMAX;
        while (lo < hi) {
            int mid = (lo + hi) >> 1;
            if (L[mid] > my) lo = mid + 1; else hi = mid;
        }
        atomicAdd(&s_rank[i], lo);
    }
    __syncthreads();

    if (tid < NMSMAX) {
        int r = s_rank[tid];
        if (r < TOPK) {
            unsigned long long key = keys[c0 * NMSMAX + tid];
            unsigned hi32 = (unsigned)(key >> 32);
            float* o = out + ((size_t)b * TOPK + r) * 6;
            if (hi32 != FM_NEGINF) {
                float4 box = g_selbox[bc * NMSMAX + tid];
                o[0] = (float)c0 + 1.0f;
                o[1] = funmap(hi32);
                o[2] = box.x; o[3] = box.y; o[4] = box.z; o[5] = box.w;
            } else {
                o[0] = 1.0f; o[1] = 0.0f;
                o[2] = 0.0f; o[3] = 0.0f; o[4] = 0.0f; o[5] = 0.0f;
            }
        }
    }
    if (tid == 0) g_candcnt[bc] = 0;   // reset for next replay (stream-ordered)
}

// -----------------------------------------------------------------------------
extern "C" void kernel_launch(void* const* d_in, const int* in_sizes, int n_in,
                              void* d_out, int out_size)
{
    const float* y = (const float*)d_in[0];
    float* out = (float*)d_out;
    decode_kernel<<<BB * NTILES, 256>>>(y);
    nms_kernel<<<NBC, 32>>>(y);
    topk_kernel<<<NBC, TK_T>>>(out);
}

// round 17
// speedup vs baseline: 1.1805x; 1.0283x over previous
#include <cuda_runtime.h>
#include <math.h>
#include <stdint.h>

#define BB     32
#define NN     8732
#define NCLS   20
#define DCOL   33
#define NMSMAX 100
#define TOPK   200
#define CONF_T 0.01f
#define IOU_T  0.45f
#define TILE   128
#define NTILES 69            // ceil(8732/128)
#define NBC    (BB * NCLS)   // 640
#define CAP    384
#define STAGE  8             // staged slots per (tile,class); ~3.2 expected
#define TK_T   256

// ---------------- scratch ----------------
__device__ float4             g_boxes   [(size_t)BB * NN];
__device__ int                g_candcnt [NBC];            // zero-init; topk resets
__device__ unsigned long long g_cand    [NBC * CAP];
__device__ float              g_selscore[NBC * NMSMAX];
__device__ float4             g_selbox  [NBC * NMSMAX];

// monotonic float <-> u32 order-preserving map
__device__ __forceinline__ unsigned fmap(float f) {
    unsigned u = __float_as_uint(f);
    return (u & 0x80000000u) ? ~u : (u | 0x80000000u);
}
__device__ __forceinline__ float funmap(unsigned u) {
    return __uint_as_float((u & 0x80000000u) ? (u & 0x7FFFFFFFu) : ~u);
}
#define FM_NEGINF 0x007FFFFFu   // fmap(-inf)

__device__ __forceinline__ float4 decode_box_row(const float* __restrict__ r)
{
    float cx_p = r[21], cy_p = r[22], w_p = r[23], h_p = r[24];
    float xa1  = r[25], ya1  = r[26], xa2 = r[27], ya2 = r[28];
    float vcx  = r[29], vcy  = r[30], vw  = r[31], vh  = r[32];
    float w_a = xa2 - xa1, h_a = ya2 - ya1;
    float cx_a = (xa2 + xa1) * 0.5f, cy_a = (ya2 + ya1) * 0.5f;
    float cx = cx_p * vcx * w_a + cx_a;
    float cy = cy_p * vcy * h_a + cy_a;
    float w  = expf(w_p * vw) * w_a;
    float h  = expf(h_p * vh) * h_a;
    float4 o;
    o.x = (cx - 0.5f * w) * 512.0f;
    o.y = (cy - 0.5f * h) * 512.0f;
    o.z = (cx + 0.5f * w) * 512.0f;
    o.w = (cy + 0.5f * h) * 512.0f;
    return o;
}

// ---------------- phase 1: decode + staged candidate filter ----------------
__global__ void __launch_bounds__(256) decode_kernel(const float* __restrict__ y)
{
    __shared__ __align__(16) float sh[TILE * DCOL];
    __shared__ unsigned long long s_skey[NCLS * STAGE];   // 1.28 KB
    __shared__ int s_scnt[NCLS];
    __shared__ int s_sbase[NCLS];

    const int tid = threadIdx.x;
    int blk = blockIdx.x;
    int b   = blk / NTILES;
    int t   = blk % NTILES;
    int n0  = t * TILE;
    int count = min(TILE, NN - n0);

    {   // vectorized tile load (count*DCOL % 4 == 0, base 16B-aligned)
        const float4* src4 = (const float4*)(y + ((size_t)b * NN + n0) * DCOL);
        float4* sh4 = (float4*)sh;
        int n4 = (count * DCOL) >> 2;
        for (int i = tid; i < n4; i += 256) sh4[i] = src4[i];
    }
    if (tid < NCLS) s_scnt[tid] = 0;
    __syncthreads();

    if (count == TILE) {
        for (int k = tid; k < NCLS * TILE; k += 256) {
            int c  = k >> 7;
            int nn = k & (TILE - 1);
            float s = sh[nn * DCOL + 1 + c];
            if (s >= 0.975f) {
                unsigned m = fmap(s);
                unsigned long long key = ((unsigned long long)m << 32) |
                                         (unsigned)(0xFFFFFFFFu - (unsigned)(n0 + nn));
                int p = atomicAdd(&s_scnt[c], 1);
                if (p < STAGE) s_skey[c * STAGE + p] = key;
                else {
                    int bc = b * NCLS + c;
                    int q = atomicAdd(&g_candcnt[bc], 1);
                    if (q < CAP) g_cand[bc * CAP + q] = key;
                }
            }
        }
    } else {
        for (int k = tid; k < NCLS * count; k += 256) {
            int c  = k / count;
            int nn = k - c * count;
            float s = sh[nn * DCOL + 1 + c];
            if (s >= 0.975f) {
                unsigned m = fmap(s);
                unsigned long long key = ((unsigned long long)m << 32) |
                                         (unsigned)(0xFFFFFFFFu - (unsigned)(n0 + nn));
                int p = atomicAdd(&s_scnt[c], 1);
                if (p < STAGE) s_skey[c * STAGE + p] = key;
                else {
                    int bc = b * NCLS + c;
                    int q = atomicAdd(&g_candcnt[bc], 1);
                    if (q < CAP) g_cand[bc * CAP + q] = key;
                }
            }
        }
    }
    __syncthreads();

    if (tid < NCLS) {
        int n = min(s_scnt[tid], STAGE);
        s_sbase[tid] = (n > 0) ? atomicAdd(&g_candcnt[b * NCLS + tid], n) : 0;
    }
    __syncthreads();
    if (tid < NCLS * STAGE) {       // single predicated flush: 160 threads
        int c = tid >> 3;           // STAGE = 8
        int j = tid & 7;
        if (j < min(s_scnt[c], STAGE)) {
            int q = s_sbase[c] + j;
            if (q < CAP) g_cand[(b * NCLS + c) * CAP + q] = s_skey[tid];
        }
    }

    if (tid < count)
        g_boxes[(size_t)b * NN + n0 + tid] = decode_box_row(sh + tid * DCOL);
}

// ---------------- phase 2: warp-scoped NMS, ONE warp-block per (b,c) --------
struct WarpSmem {
    float4   allbox[512];    // boxes in sorted order
    float4   kbox[NMSMAX];   // kept positive-area boxes (persist across windows)
    float    karea[NMSMAX];
    unsigned keyA[256];      // 32-bit compressed keys, window A
    unsigned keyB[256];      // 32-bit compressed keys, window B
};

// -------- 64-bit exact path (R11-proven): sort + serial greedy --------------
template<int SLOTS>
__device__ __forceinline__ void process_window_impl(
    const unsigned long long* __restrict__ src, int cnt, const float4* __restrict__ bx,
    int bc, WarpSmem& W, int lane, int& ns, int& nkp)
{
    constexpr int LOG2N = (SLOTS == 8) ? 8 : 9;

    unsigned long long key[SLOTS];
    #pragma unroll
    for (int s = 0; s < SLOTS; ++s) {
        int p = s * 32 + lane;
        key[s] = (p < cnt) ? src[p] : 0ull;
    }
    #pragma unroll
    for (int ksl = 1; ksl <= LOG2N; ++ksl) {
        const int ks = 1 << ksl;
        #pragma unroll
        for (int j = ks >> 1; j >= 32; j >>= 1) {
            const int js = j >> 5;
            #pragma unroll
            for (int s = 0; s < SLOTS; ++s) {
                const int sp = s ^ js;
                if (sp > s) {
                    bool descSeg = (((s * 32) & ks) == 0);
                    unsigned long long a = key[s], b2 = key[sp];
                    if (descSeg ? (a < b2) : (a > b2)) { key[s] = b2; key[sp] = a; }
                }
            }
        }
        for (int j = (ks >> 1) < 32 ? (ks >> 1) : 16; j > 0; j >>= 1) {
            #pragma unroll
            for (int s = 0; s < SLOTS; ++s) {
                int p = s * 32 + lane;
                unsigned long long pv = __shfl_xor_sync(0xFFFFFFFFu, key[s], j);
                bool takeMax = (((lane & j) == 0) == ((p & ks) == 0));
                unsigned long long mx = (key[s] > pv) ? key[s] : pv;
                unsigned long long mn = (key[s] > pv) ? pv : key[s];
                key[s] = takeMax ? mx : mn;
            }
        }
    }

    float area[SLOTS];
    #pragma unroll
    for (int s = 0; s < SLOTS; ++s) {
        int p = s * 32 + lane;
        float4 Bt = make_float4(0.f, 0.f, 0.f, 0.f);
        if (key[s] != 0ull) {
            int idx = (int)(0xFFFFFFFFu - (unsigned)(key[s] & 0xFFFFFFFFull));
            Bt = __ldg(&bx[idx]);
        }
        W.allbox[p] = Bt;
        area[s] = fmaxf(Bt.z - Bt.x, 0.0f) * fmaxf(Bt.w - Bt.y, 0.0f);
    }
    __syncwarp();

    #pragma unroll 1
    for (int s = 0; s < SLOTS; ++s) {
        if (ns >= NMSMAX) break;
        unsigned validm = __ballot_sync(0xFFFFFFFFu, key[s] != 0ull);
        if (!validm) break;
        unsigned zerom  = __ballot_sync(0xFFFFFFFFu, area[s] == 0.0f) & validm;
        unsigned posm   = validm & ~zerom;
        unsigned km = zerom;
        while (posm) {
            int l = __ffs(posm) - 1;
            posm &= posm - 1u;
            float4 Bt = W.allbox[s * 32 + l];
            float  at = __shfl_sync(0xFFFFFFFFu, area[s], l);
            bool sup = false;
            for (int j2 = lane; j2 < nkp; j2 += 32) {
                float4 Kj = W.kbox[j2];
                float ix1 = fmaxf(Kj.x, Bt.x), iy1 = fmaxf(Kj.y, Bt.y);
                float ix2 = fminf(Kj.z, Bt.z), iy2 = fminf(Kj.w, Bt.w);
                float inter = fmaxf(ix2 - ix1, 0.0f) * fmaxf(iy2 - iy1, 0.0f);
                float iou = inter / (W.karea[j2] + at - inter + 1e-9f);
                sup |= (iou > IOU_T);
            }
            if (!__any_sync(0xFFFFFFFFu, sup)) {
                km |= 1u << l;
                if (nkp < NMSMAX) {
                    if (lane == 0) { W.kbox[nkp] = Bt; W.karea[nkp] = at; }
                    nkp++;
                    __syncwarp();
                }
            }
        }
        int myr = ns + __popc(km & ((1u << lane) - 1u));
        if (((km >> lane) & 1u) && myr < NMSMAX) {
            int o = bc * NMSMAX + myr;
            g_selscore[o] = funmap((unsigned)(key[s] >> 32));
            g_selbox[o]   = W.allbox[s * 32 + lane];
        }
        ns += __popc(km);
    }
}

__device__ __noinline__ void process_window8(
    const unsigned long long* src, int cnt, const float4* bx,
    int bc, WarpSmem& W, int lane, int& ns, int& nkp)
{ process_window_impl<8>(src, cnt, bx, bc, W, lane, ns, nkp); }

__device__ __noinline__ void process_window16(
    const unsigned long long* src, int cnt, const float4* bx,
    int bc, WarpSmem& W, int lane, int& ns, int& nkp)
{ process_window_impl<16>(src, cnt, bx, bc, W, lane, ns, nkp); }

// -------- 32-bit compressed-key fast path (R14 measured-best) ---------------
template<int SLOTS>
__device__ __forceinline__ void process32_impl(
    const unsigned* __restrict__ skey, int cnt, unsigned base,
    const float4* __restrict__ bx, int bc, WarpSmem& W, int lane, int& ns, int& nkp)
{
    constexpr int LOG2N = (SLOTS == 4) ? 7 : 8;

    unsigned key[SLOTS];
    #pragma unroll
    for (int s = 0; s < SLOTS; ++s) {
        int p = s * 32 + lane;
        key[s] = (p < cnt) ? skey[p] : 0u;
    }

    #pragma unroll
    for (int ksl = 1; ksl <= LOG2N; ++ksl) {
        const int ks = 1 << ksl;
        #pragma unroll
        for (int j = ks >> 1; j >= 32; j >>= 1) {
            const int js = j >> 5;
            #pragma unroll
            for (int s = 0; s < SLOTS; ++s) {
                const int sp = s ^ js;
                if (sp > s) {
                    bool descSeg = (((s * 32) & ks) == 0);
                    unsigned a = key[s], b2 = key[sp];
                    if (descSeg ? (a < b2) : (a > b2)) { key[s] = b2; key[sp] = a; }
                }
            }
        }
        for (int j = (ks >> 1) < 32 ? (ks >> 1) : 16; j > 0; j >>= 1) {
            #pragma unroll
            for (int s = 0; s < SLOTS; ++s) {
                int p = s * 32 + lane;
                unsigned pv = __shfl_xor_sync(0xFFFFFFFFu, key[s], j);
                bool takeMax = (((lane & j) == 0) == ((p & ks) == 0));
                unsigned mx = (key[s] > pv) ? key[s] : pv;
                unsigned mn = (key[s] > pv) ? pv : key[s];
                key[s] = takeMax ? mx : mn;
            }
        }
    }

    float area[SLOTS];
    #pragma unroll
    for (int s = 0; s < SLOTS; ++s) {
        int p = s * 32 + lane;
        float4 Bt = make_float4(0.f, 0.f, 0.f, 0.f);
        if (key[s] != 0u) {
            int idx = 16383 - (int)(key[s] & 0x3FFFu);
            Bt = __ldg(&bx[idx]);
        }
        W.allbox[p] = Bt;
        area[s] = fmaxf(Bt.z - Bt.x, 0.0f) * fmaxf(Bt.w - Bt.y, 0.0f);
    }
    __syncwarp();

    #pragma unroll 1
    for (int s = 0; s < SLOTS; ++s) {
        if (ns >= NMSMAX) break;
        unsigned validm = __ballot_sync(0xFFFFFFFFu, key[s] != 0u);
        if (!validm) break;
        unsigned zerom  = __ballot_sync(0xFFFFFFFFu, area[s] == 0.0f) & validm;
        unsigned posm   = validm & ~zerom;
        unsigned km = zerom;
        while (posm) {
            int l = __ffs(posm) - 1;
            posm &= posm - 1u;
            float4 Bt = W.allbox[s * 32 + l];
            float  at = __shfl_sync(0xFFFFFFFFu, area[s], l);
            bool sup = false;
            for (int j2 = lane; j2 < nkp; j2 += 32) {
                float4 Kj = W.kbox[j2];
                float ix1 = fmaxf(Kj.x, Bt.x), iy1 = fmaxf(Kj.y, Bt.y);
                float ix2 = fminf(Kj.z, Bt.z), iy2 = fminf(Kj.w, Bt.w);
                float inter = fmaxf(ix2 - ix1, 0.0f) * fmaxf(iy2 - iy1, 0.0f);
                float iou = inter / (W.karea[j2] + at - inter + 1e-9f);
                sup |= (iou > IOU_T);
            }
            if (!__any_sync(0xFFFFFFFFu, sup)) {
                km |= 1u << l;
                if (nkp < NMSMAX) {
                    if (lane == 0) { W.kbox[nkp] = Bt; W.karea[nkp] = at; }
                    nkp++;
                    __syncwarp();
                }
            }
        }
        int myr = ns + __popc(km & ((1u << lane) - 1u));
        if (((km >> lane) & 1u) && myr < NMSMAX) {
            int o = bc * NMSMAX + myr;
            g_selscore[o] = funmap(base + (key[s] >> 14));
            g_selbox[o]   = W.allbox[s * 32 + lane];
        }
        ns += __popc(km);
    }
}

__device__ __forceinline__ void process32_4(
    const unsigned* skey, int cnt, unsigned base, const float4* bx,
    int bc, WarpSmem& W, int lane, int& ns, int& nkp)
{ process32_impl<4>(skey, cnt, base, bx, bc, W, lane, ns, nkp); }

__device__ __noinline__ void process32_8(
    const unsigned* skey, int cnt, unsigned base, const float4* bx,
    int bc, WarpSmem& W, int lane, int& ns, int& nkp)
{ process32_impl<8>(skey, cnt, base, bx, bc, W, lane, ns, nkp); }

__global__ void __launch_bounds__(32) nms_kernel(const float* __restrict__ y)
{
    __shared__ WarpSmem W;
    const int lane = threadIdx.x;
    const int bc   = blockIdx.x;
    const int b    = bc / NCLS;
    const int c    = bc - b * NCLS;
    const float4* bx = g_boxes + (size_t)b * NN;

    const unsigned LO  = fmap(0.975f);
    const unsigned HI2 = fmap(0.9875f);
    const unsigned below = (1u << lane) - 1u;
    int ns = 0, nkp = 0;

    int cnt0 = g_candcnt[bc];
    bool haveList = (cnt0 <= CAP);
    unsigned nextHi = haveList ? LO : 0xFFFFFFFFu;

    if (haveList && cnt0 > 0) {
        const unsigned long long* src = g_cand + bc * CAP;
        int cA = 0, cB = 0;
        for (int s = 0; s * 32 < cnt0; ++s) {
            int p = s * 32 + lane;
            unsigned long long k = (p < cnt0) ? src[p] : 0ull;
            unsigned m = (unsigned)(k >> 32);
            bool valid = (p < cnt0);
            bool inA = valid && (m >= HI2);
            bool inB = valid && (m < HI2);
            unsigned mA = __ballot_sync(0xFFFFFFFFu, inA);
            unsigned mB = __ballot_sync(0xFFFFFFFFu, inB);
            unsigned inv14 = (unsigned)k & 0x3FFFu;
            if (inA) {
                int q = cA + __popc(mA & below);
                if (q < 256) W.keyA[q] = ((m - HI2) << 14) | inv14;
            }
            if (inB) {
                int q = cB + __popc(mB & below);
                if (q < 256) W.keyB[q] = ((m - LO) << 14) | inv14;
            }
            cA += __popc(mA);
            cB += __popc(mB);
        }
        __syncwarp();

        if (cA <= 256 && cB <= 256) {
            if (cA > 0) {
                if (cA <= 128) process32_4(W.keyA, cA, HI2, bx, bc, W, lane, ns, nkp);
                else           process32_8(W.keyA, cA, HI2, bx, bc, W, lane, ns, nkp);
            }
            if (ns < NMSMAX && cB > 0) {
                if (cB <= 128) process32_4(W.keyB, cB, LO, bx, bc, W, lane, ns, nkp);
                else           process32_8(W.keyB, cB, LO, bx, bc, W, lane, ns, nkp);
            }
        } else {
            if (cnt0 <= 256) process_window8 (src, cnt0, bx, bc, W, lane, ns, nkp);
            else             process_window16(src, cnt0, bx, bc, W, lane, ns, nkp);
        }
    }

    // exact continuation: descend score windows over raw y (warp-scoped, rare)
    while (ns < NMSMAX && nextHi > 0) {
        unsigned lo2 = 0, hi2 = nextHi;
        int cnt;
        for (;;) {
            cnt = 0;
            for (int i = lane; i < NN; i += 32) {
                float v = y[((size_t)b * NN + i) * DCOL + 1 + c];
                bool take = false; unsigned m = 0;
                if (v > CONF_T) { m = fmap(v); take = (m >= lo2 && m < hi2); }
                unsigned msk = __ballot_sync(0xFFFFFFFFu, take);
                if (take) {
                    int off = cnt + __popc(msk & below);
                    if (off < CAP)
                        g_cand[bc * CAP + off] = ((unsigned long long)m << 32) |
                                                 (unsigned)(0xFFFFFFFFu - (unsigned)i);
                }
                cnt += __popc(msk);
            }
            if (cnt <= CAP || hi2 - lo2 <= 1) break;
            lo2 = lo2 + ((hi2 - lo2) >> 1);
        }
        if (cnt > CAP) cnt = CAP;
        __threadfence_block();
        __syncwarp();
        if (cnt > 0) {
            if (cnt <= 256) process_window8 (g_cand + bc * CAP, cnt, bx, bc, W, lane, ns, nkp);
            else            process_window16(g_cand + bc * CAP, cnt, bx, bc, W, lane, ns, nkp);
        }
        nextHi = lo2;
    }

    for (int j = ns + lane; j < NMSMAX; j += 32)
        g_selscore[bc * NMSMAX + j] = -INFINITY;
}

// ---------------- phase 3: rank-scatter top-200, 32-bit keys ----------------
// key32 = (mp << 11) | (2047 - k), mp = fmap(s) - fmap(0.975) + 1 (19 bits).
// Exact total order: score desc, flat-index asc; invalid (mp=0) below all
// valid, index-asc among themselves — identical to the 64-bit semantics.
// Scores outside [0.975, ~1.0125) (only reachable via the continuation path)
// trigger the 64-bit fallback in the same smem union.
__global__ void __launch_bounds__(TK_T) topk_kernel(float* __restrict__ out)
{
    const int bc  = blockIdx.x;
    const int b   = bc / NCLS;
    const int c0  = bc - b * NCLS;
    const int tid = threadIdx.x;
    const int NK  = NCLS * NMSMAX;

    __shared__ __align__(16) char kraw[NCLS * NMSMAX * 8];   // 16 KB union
    __shared__ int s_rank[NMSMAX];
    __shared__ int s_fb;

    unsigned*           k32 = (unsigned*)kraw;
    unsigned long long* k64 = (unsigned long long*)kraw;

    if (tid == 0) s_fb = 0;
    if (tid < NMSMAX) s_rank[tid] = tid;
    __syncthreads();

    const unsigned LOq = fmap(0.975f);
    for (int k = tid; k < NK; k += TK_T) {
        float s = g_selscore[b * NK + k];
        unsigned mp;
        if (s == -INFINITY) mp = 0u;
        else {
            unsigned d = fmap(s) - LOq;      // wraps huge if s < 0.975
            if (d >= 0x7FFFFu) s_fb = 1;     // out of 19-bit window
            mp = d + 1u;
        }
        k32[k] = (mp << 11) | (unsigned)(2047 - k);
    }
    __syncthreads();

    if (!s_fb) {
        // ---- 32-bit search path ----
        for (int u = tid; u < (NCLS - 1) * NMSMAX; u += TK_T) {
            int j = u / NMSMAX;
            int i = u - j * NMSMAX;
            int cc = j + (j >= c0);
            unsigned my = k32[c0 * NMSMAX + i];
            const unsigned* L = k32 + cc * NMSMAX;
            int lo = 0, hi = NMSMAX;
            while (lo < hi) {
                int mid = (lo + hi) >> 1;
                if (L[mid] > my) lo = mid + 1; else hi = mid;
            }
            atomicAdd(&s_rank[i], lo);
        }
        __syncthreads();

        if (tid < NMSMAX) {
            int r = s_rank[tid];
            if (r < TOPK) {
                unsigned key = k32[c0 * NMSMAX + tid];
                unsigned mp = key >> 11;
                float* o = out + ((size_t)b * TOPK + r) * 6;
                if (mp != 0u) {
                    float4 box = g_selbox[bc * NMSMAX + tid];
                    o[0] = (float)c0 + 1.0f;
                    o[1] = funmap(mp - 1u + LOq);     // bit-exact score
                    o[2] = box.x; o[3] = box.y; o[4] = box.z; o[5] = box.w;
                } else {
                    o[0] = 1.0f; o[1] = 0.0f;
                    o[2] = 0.0f; o[3] = 0.0f; o[4] = 0.0f; o[5] = 0.0f;
                }
            }
        }
    } else {
        // ---- 64-bit exact fallback (R16-proven) ----
        __syncthreads();
        for (int k = tid; k < NK; k += TK_T) {
            float s = g_selscore[b * NK + k];
            k64[k] = ((unsigned long long)fmap(s) << 32) |
                     (unsigned)(0xFFFFFFFFu - (unsigned)k);
        }
        __syncthreads();
        for (int u = tid; u < (NCLS - 1) * NMSMAX; u += TK_T) {
            int j = u / NMSMAX;
            int i = u - j * NMSMAX;
            int cc = j + (j >= c0);
            unsigned long long my = k64[c0 * NMSMAX + i];
            const unsigned long long* L = k64 + cc * NMSMAX;
            int lo = 0, hi = NMSMAX;
            while (lo < hi) {
                int mid = (lo + hi) >> 1;
                if (L[mid] > my) lo = mid + 1; else hi = mid;
            }
            atomicAdd(&s_rank[i], lo);
        }
        __syncthreads();
        if (tid < NMSMAX) {
            int r = s_rank[tid];
            if (r < TOPK) {
                unsigned long long key = k64[c0 * NMSMAX + tid];
                unsigned hi32 = (unsigned)(key >> 32);
                float* o = out + ((size_t)b * TOPK + r) * 6;
                if (hi32 != FM_NEGINF) {
                    float4 box = g_selbox[bc * NMSMAX + tid];
                    o[0] = (float)c0 + 1.0f;
                    o[1] = funmap(hi32);
                    o[2] = box.x; o[3] = box.y; o[4] = box.z; o[5] = box.w;
                } else {
                    o[0] = 1.0f; o[1] = 0.0f;
                    o[2] = 0.0f; o[3] = 0.0f; o[4] = 0.0f; o[5] = 0.0f;
                }
            }
        }
    }
    if (tid == 0) g_candcnt[bc] = 0;   // reset for next replay (stream-ordered)
}

// -----------------------------------------------------------------------------
extern "C" void kernel_launch(void* const* d_in, const int* in_sizes, int n_in,
                              void* d_out, int out_size)
{
    const float* y = (const float*)d_in[0];
    float* out = (float*)d_out;
    decode_kernel<<<BB * NTILES, 256>>>(y);
    nms_kernel<<<NBC, 32>>>(y);
    topk_kernel<<<NBC, TK_T>>>(out);
}